// round 1
// baseline (speedup 1.0000x reference)
#include <cuda_runtime.h>
#include <math.h>

#define NN 8
#define CC 1024
#define BB 2048
#define EPS 1e-12f

// ---- scratch (device globals; no allocation allowed) ----
__device__ float g_K[(size_t)NN * CC * BB];   // 64 MB
__device__ float g_Q[(size_t)NN * CC * BB];   // 64 MB
__device__ float g_Y[(size_t)NN * BB * BB];   // 128 MB (holds Y, then exp, then SM in-place)
__device__ float g_DK2[NN * BB];
__device__ float g_DQ2[NN * BB];

#define BM 64
#define BN 64
#define BK 16
#define TM 4
#define TN 4
// 256 threads: 16x16 thread tile, each thread computes 4x4 outputs

// ---------------------------------------------------------------------------
// Stage 1: K = Wk@X + bk, Q = Wq@X + bq   (per n; share X tiles)
// K[o,b] = sum_c W[o,c] * X[c,b]
// ---------------------------------------------------------------------------
__global__ __launch_bounds__(256)
void proj_kernel(const float* __restrict__ X,
                 const float* __restrict__ Wk, const float* __restrict__ bk,
                 const float* __restrict__ Wq, const float* __restrict__ bq)
{
    const int n = blockIdx.z;
    const float* Xn = X + (size_t)n * CC * BB;
    float* Kn = g_K + (size_t)n * CC * BB;
    float* Qn = g_Q + (size_t)n * CC * BB;

    const int row0 = blockIdx.y * BM;   // output channel o
    const int col0 = blockIdx.x * BN;   // column b

    __shared__ float sWk[BM][BK];
    __shared__ float sWq[BM][BK];
    __shared__ float sX[BK][BN];

    const int tid = threadIdx.x;
    const int tx = tid & 15;
    const int ty = tid >> 4;

    float accK[TM][TN] = {};
    float accQ[TM][TN] = {};

    for (int k0 = 0; k0 < CC; k0 += BK) {
        #pragma unroll
        for (int i = tid; i < BM * BK; i += 256) {
            int r = i / BK, c = i % BK;
            sWk[r][c] = Wk[(size_t)(row0 + r) * CC + k0 + c];
            sWq[r][c] = Wq[(size_t)(row0 + r) * CC + k0 + c];
        }
        #pragma unroll
        for (int i = tid; i < BK * BN; i += 256) {
            int r = i / BN, c = i % BN;
            sX[r][c] = Xn[(size_t)(k0 + r) * BB + col0 + c];
        }
        __syncthreads();

        #pragma unroll
        for (int kk = 0; kk < BK; kk++) {
            float ak[TM], aq[TM];
            #pragma unroll
            for (int i = 0; i < TM; i++) {
                ak[i] = sWk[ty * TM + i][kk];
                aq[i] = sWq[ty * TM + i][kk];
            }
            float4 bv = *reinterpret_cast<const float4*>(&sX[kk][tx * TN]);
            float b[TN] = {bv.x, bv.y, bv.z, bv.w};
            #pragma unroll
            for (int i = 0; i < TM; i++)
                #pragma unroll
                for (int j = 0; j < TN; j++) {
                    accK[i][j] = fmaf(ak[i], b[j], accK[i][j]);
                    accQ[i][j] = fmaf(aq[i], b[j], accQ[i][j]);
                }
        }
        __syncthreads();
    }

    #pragma unroll
    for (int i = 0; i < TM; i++) {
        int o = row0 + ty * TM + i;
        float bkv = bk[o];
        float bqv = bq[o];
        #pragma unroll
        for (int j = 0; j < TN; j++) {
            int b = col0 + tx * TN + j;
            Kn[(size_t)o * BB + b] = accK[i][j] + bkv;
            Qn[(size_t)o * BB + b] = accQ[i][j] + bqv;
        }
    }
}

// ---------------------------------------------------------------------------
// Stage 2: DK2[n,b] = sum_c K[n,c,b]^2 ; DQ2 likewise
// ---------------------------------------------------------------------------
__global__ __launch_bounds__(256)
void sq_kernel()
{
    int idx = blockIdx.x * 256 + threadIdx.x;   // over n*BB
    int n = idx / BB;
    int b = idx % BB;
    const float* Kn = g_K + (size_t)n * CC * BB + b;
    const float* Qn = g_Q + (size_t)n * CC * BB + b;
    float sk = 0.f, sq = 0.f;
    #pragma unroll 4
    for (int c = 0; c < CC; c++) {
        float kv = Kn[(size_t)c * BB];
        float qv = Qn[(size_t)c * BB];
        sk = fmaf(kv, kv, sk);
        sq = fmaf(qv, qv, sq);
    }
    g_DK2[idx] = sk;
    g_DQ2[idx] = sq;
}

// ---------------------------------------------------------------------------
// Stage 3: Y[n,b,k] = (sum_c Q[n,c,b] K[n,c,k]) / sqrt(max(DQ2[b]*DK2[k],EPS))
// A = Q^T (loaded as [BK][BM], coalesced), B = K
// ---------------------------------------------------------------------------
__global__ __launch_bounds__(256)
void score_kernel()
{
    const int n = blockIdx.z;
    const float* Qn = g_Q + (size_t)n * CC * BB;
    const float* Kn = g_K + (size_t)n * CC * BB;
    float* Yn = g_Y + (size_t)n * BB * BB;

    const int row0 = blockIdx.y * BM;   // b
    const int col0 = blockIdx.x * BN;   // k

    __shared__ float sQ[BK][BM];
    __shared__ float sK[BK][BN];

    const int tid = threadIdx.x;
    const int tx = tid & 15;
    const int ty = tid >> 4;

    float acc[TM][TN] = {};

    for (int k0 = 0; k0 < CC; k0 += BK) {
        #pragma unroll
        for (int i = tid; i < BK * BM; i += 256) {
            int r = i / BM, c = i % BM;
            sQ[r][c] = Qn[(size_t)(k0 + r) * BB + row0 + c];
        }
        #pragma unroll
        for (int i = tid; i < BK * BN; i += 256) {
            int r = i / BN, c = i % BN;
            sK[r][c] = Kn[(size_t)(k0 + r) * BB + col0 + c];
        }
        __syncthreads();

        #pragma unroll
        for (int kk = 0; kk < BK; kk++) {
            float4 av = *reinterpret_cast<const float4*>(&sQ[kk][ty * TM]);
            float4 bv = *reinterpret_cast<const float4*>(&sK[kk][tx * TN]);
            float a[TM] = {av.x, av.y, av.z, av.w};
            float b[TN] = {bv.x, bv.y, bv.z, bv.w};
            #pragma unroll
            for (int i = 0; i < TM; i++)
                #pragma unroll
                for (int j = 0; j < TN; j++)
                    acc[i][j] = fmaf(a[i], b[j], acc[i][j]);
        }
        __syncthreads();
    }

    float dq[TM], dk[TN];
    #pragma unroll
    for (int i = 0; i < TM; i++) dq[i] = g_DQ2[n * BB + row0 + ty * TM + i];
    #pragma unroll
    for (int j = 0; j < TN; j++) dk[j] = g_DK2[n * BB + col0 + tx * TN + j];

    #pragma unroll
    for (int i = 0; i < TM; i++) {
        int b = row0 + ty * TM + i;
        #pragma unroll
        for (int j = 0; j < TN; j++) {
            int k = col0 + tx * TN + j;
            float d = sqrtf(fmaxf(dq[i] * dk[j], EPS));
            Yn[(size_t)b * BB + k] = acc[i][j] / d;
        }
    }
}

// ---------------------------------------------------------------------------
// Stage 4: softmax over b (axis=1) of Y[n,b,k], in place.
// One thread per (n,k) column; loads coalesced across threads.
// ---------------------------------------------------------------------------
__global__ __launch_bounds__(256)
void softmax_kernel()
{
    const int n = blockIdx.y;
    const int k = blockIdx.x * 256 + threadIdx.x;
    float* Yn = g_Y + (size_t)n * BB * BB + k;

    float m = -INFINITY;
    #pragma unroll 4
    for (int b = 0; b < BB; b++)
        m = fmaxf(m, Yn[(size_t)b * BB]);

    float s = 0.f;
    #pragma unroll 4
    for (int b = 0; b < BB; b++) {
        float e = expf(Yn[(size_t)b * BB] - m);
        s += e;
        Yn[(size_t)b * BB] = e;
    }

    float inv = 1.f / s;
    #pragma unroll 4
    for (int b = 0; b < BB; b++)
        Yn[(size_t)b * BB] *= inv;
}

// ---------------------------------------------------------------------------
// Stage 5: Z[n,c,k] = sum_b X[n,c,b] * SM[n,b,k]
// ---------------------------------------------------------------------------
__global__ __launch_bounds__(256)
void mix_kernel(const float* __restrict__ X, float* __restrict__ Z)
{
    const int n = blockIdx.z;
    const float* Xn = X + (size_t)n * CC * BB;
    const float* Sn = g_Y + (size_t)n * BB * BB;
    float* Zn = Z + (size_t)n * CC * BB;

    const int row0 = blockIdx.y * BM;   // c
    const int col0 = blockIdx.x * BN;   // k

    __shared__ float sA[BM][BK];
    __shared__ float sB[BK][BN];

    const int tid = threadIdx.x;
    const int tx = tid & 15;
    const int ty = tid >> 4;

    float acc[TM][TN] = {};

    for (int k0 = 0; k0 < BB; k0 += BK) {
        #pragma unroll
        for (int i = tid; i < BM * BK; i += 256) {
            int r = i / BK, c = i % BK;
            sA[r][c] = Xn[(size_t)(row0 + r) * BB + k0 + c];
        }
        #pragma unroll
        for (int i = tid; i < BK * BN; i += 256) {
            int r = i / BN, c = i % BN;
            sB[r][c] = Sn[(size_t)(k0 + r) * BB + col0 + c];
        }
        __syncthreads();

        #pragma unroll
        for (int kk = 0; kk < BK; kk++) {
            float a[TM];
            #pragma unroll
            for (int i = 0; i < TM; i++) a[i] = sA[ty * TM + i][kk];
            float4 bv = *reinterpret_cast<const float4*>(&sB[kk][tx * TN]);
            float b[TN] = {bv.x, bv.y, bv.z, bv.w};
            #pragma unroll
            for (int i = 0; i < TM; i++)
                #pragma unroll
                for (int j = 0; j < TN; j++)
                    acc[i][j] = fmaf(a[i], b[j], acc[i][j]);
        }
        __syncthreads();
    }

    #pragma unroll
    for (int i = 0; i < TM; i++) {
        int c = row0 + ty * TM + i;
        #pragma unroll
        for (int j = 0; j < TN; j++) {
            int k = col0 + tx * TN + j;
            Zn[(size_t)c * BB + k] = acc[i][j];
        }
    }
}

// ---------------------------------------------------------------------------
extern "C" void kernel_launch(void* const* d_in, const int* in_sizes, int n_in,
                              void* d_out, int out_size)
{
    const float* X    = (const float*)d_in[0];
    const float* Wk_w = (const float*)d_in[1];
    const float* Wk_b = (const float*)d_in[2];
    const float* Wq_w = (const float*)d_in[3];
    const float* Wq_b = (const float*)d_in[4];
    float* Z = (float*)d_out;

    // 1) projections
    proj_kernel<<<dim3(BB / BN, CC / BM, NN), 256>>>(X, Wk_w, Wk_b, Wq_w, Wq_b);
    // 2) squared norms
    sq_kernel<<<(NN * BB) / 256, 256>>>();
    // 3) normalized scores
    score_kernel<<<dim3(BB / BN, BB / BM, NN), 256>>>();
    // 4) softmax over query axis (in place)
    softmax_kernel<<<dim3(BB / 256, NN), 256>>>();
    // 5) output mix
    mix_kernel<<<dim3(BB / BN, CC / BM, NN), 256>>>(X, Z);
}

// round 2
// speedup vs baseline: 3.9470x; 3.9470x over previous
#include <cuda_runtime.h>
#include <math.h>
#include <stdint.h>

#define NN 8
#define CC 1024
#define BB 2048
#define EPS 1e-12f

// ---- scratch (device globals; no allocation allowed) ----
__device__ float g_K[(size_t)NN * CC * BB];   // 64 MB
__device__ float g_Q[(size_t)NN * CC * BB];   // 64 MB
__device__ float g_Y[(size_t)NN * BB * BB];   // 128 MB
__device__ float g_DK2[NN * BB];
__device__ float g_DQ2[NN * BB];

// ===========================================================================
// TF32 warp-MMA GEMM: 128x128 CTA tile, BK=16, 8 warps (4x2), warp tile 32x64,
// mma.sync.aligned.m16n8k8.row.col.f32.tf32.tf32.f32, cp.async double buffer.
// ===========================================================================
#define BM 128
#define BN 128
#define BK 16
// smem strides (padded for conflict-free fragment loads)
#define SA_RM_STRIDE 20    // A row-major: [BM][BK+4]
#define SKM_STRIDE  136    // k-major tiles: [BK][128+8]
#define SA_RM_SZ (BM * SA_RM_STRIDE)  // 2560 floats
#define SKM_SZ   (BK * SKM_STRIDE)    // 2176 floats

__device__ __forceinline__ uint32_t f2tf(float f) {
    uint32_t r;
    asm volatile("cvt.rna.tf32.f32 %0, %1;" : "=r"(r) : "f"(f));
    return r;
}

__device__ __forceinline__ void cp16(float* smem, const float* g) {
    uint32_t s = (uint32_t)__cvta_generic_to_shared(smem);
    asm volatile("cp.async.cg.shared.global [%0], [%1], 16;" :: "r"(s), "l"(g));
}
__device__ __forceinline__ void cp_commit() {
    asm volatile("cp.async.commit_group;");
}

__device__ __forceinline__ void mma_tf32(float (&d)[4], const uint32_t (&a)[4],
                                         const uint32_t (&b)[2]) {
    asm volatile(
        "mma.sync.aligned.m16n8k8.row.col.f32.tf32.tf32.f32 "
        "{%0,%1,%2,%3}, {%4,%5,%6,%7}, {%8,%9}, {%0,%1,%2,%3};"
        : "+f"(d[0]), "+f"(d[1]), "+f"(d[2]), "+f"(d[3])
        : "r"(a[0]), "r"(a[1]), "r"(a[2]), "r"(a[3]),
          "r"(b[0]), "r"(b[1]));
}

// MODE: 0 = proj (C = A@B + bias), 1 = score (C = A^T@B / sqrt(dq*dk)), 2 = mix
// AKM: A tile stored k-major in smem (A is column-major in gmem: elem(m,k)=A[k*lda+m])
template <int MODE, int KDIM, bool AKM>
__global__ __launch_bounds__(256, 1)
void gemm_tf32(const float* __restrict__ A, int lda, size_t strA,
               const float* __restrict__ B, int ldb, size_t strB,
               float* __restrict__ C, int ldc, size_t strC,
               const float* __restrict__ bias,
               const float* __restrict__ dq2_all,
               const float* __restrict__ dk2_all)
{
    constexpr int SA_SZ = AKM ? SKM_SZ : SA_RM_SZ;
    __shared__ float sA[2][SA_SZ];
    __shared__ float sB[2][SKM_SZ];

    const int n = blockIdx.z;
    const float* An = A + (size_t)n * strA;
    const float* Bn = B + (size_t)n * strB;
    float* Cn = C + (size_t)n * strC;

    const int row0 = blockIdx.y * BM;
    const int col0 = blockIdx.x * BN;

    const int tid = threadIdx.x;
    const int lane = tid & 31;
    const int warp = tid >> 5;
    const int wm = warp >> 1;   // 0..3
    const int wn = warp & 1;    // 0..1
    const int lr = lane >> 2;   // 0..7
    const int lc = lane & 3;    // 0..3

    float acc[2][8][4] = {};

    // ---- tile loaders ----
    auto loadA = [&](float* s, int k0) {
        if (!AKM) {
            #pragma unroll
            for (int i = tid; i < 512; i += 256) {
                int r = i >> 2, sg = i & 3;
                cp16(s + r * SA_RM_STRIDE + sg * 4,
                     An + (size_t)(row0 + r) * lda + k0 + sg * 4);
            }
        } else {
            #pragma unroll
            for (int i = tid; i < 512; i += 256) {
                int r = i >> 5, sg = i & 31;
                cp16(s + r * SKM_STRIDE + sg * 4,
                     An + (size_t)(k0 + r) * lda + row0 + sg * 4);
            }
        }
    };
    auto loadB = [&](float* s, int k0) {
        #pragma unroll
        for (int i = tid; i < 512; i += 256) {
            int r = i >> 5, sg = i & 31;
            cp16(s + r * SKM_STRIDE + sg * 4,
                 Bn + (size_t)(k0 + r) * ldb + col0 + sg * 4);
        }
    };

    constexpr int KTILES = KDIM / BK;

    // prologue
    loadA(sA[0], 0);
    loadB(sB[0], 0);
    cp_commit();

    for (int kt = 0; kt < KTILES; kt++) {
        const int buf = kt & 1;
        if (kt + 1 < KTILES) {
            loadA(sA[buf ^ 1], (kt + 1) * BK);
            loadB(sB[buf ^ 1], (kt + 1) * BK);
            cp_commit();
            asm volatile("cp.async.wait_group 1;");
        } else {
            asm volatile("cp.async.wait_group 0;");
        }
        __syncthreads();

        const float* cA = sA[buf];
        const float* cB = sB[buf];

        #pragma unroll
        for (int ks = 0; ks < 2; ks++) {
            const int kb = ks * 8;
            uint32_t af[2][4];
            uint32_t bf[8][2];

            #pragma unroll
            for (int mi = 0; mi < 2; mi++) {
                const int r = wm * 32 + mi * 16 + lr;
                const int c = kb + lc;
                if (!AKM) {
                    af[mi][0] = f2tf(cA[r * SA_RM_STRIDE + c]);
                    af[mi][1] = f2tf(cA[(r + 8) * SA_RM_STRIDE + c]);
                    af[mi][2] = f2tf(cA[r * SA_RM_STRIDE + c + 4]);
                    af[mi][3] = f2tf(cA[(r + 8) * SA_RM_STRIDE + c + 4]);
                } else {
                    af[mi][0] = f2tf(cA[c * SKM_STRIDE + r]);
                    af[mi][1] = f2tf(cA[c * SKM_STRIDE + r + 8]);
                    af[mi][2] = f2tf(cA[(c + 4) * SKM_STRIDE + r]);
                    af[mi][3] = f2tf(cA[(c + 4) * SKM_STRIDE + r + 8]);
                }
            }
            #pragma unroll
            for (int ni = 0; ni < 8; ni++) {
                const int kr = kb + lc;
                const int nc = wn * 64 + ni * 8 + lr;
                bf[ni][0] = f2tf(cB[kr * SKM_STRIDE + nc]);
                bf[ni][1] = f2tf(cB[(kr + 4) * SKM_STRIDE + nc]);
            }
            #pragma unroll
            for (int mi = 0; mi < 2; mi++)
                #pragma unroll
                for (int ni = 0; ni < 8; ni++)
                    mma_tf32(acc[mi][ni], af[mi], bf[ni]);
        }
        __syncthreads();
    }

    // ---- epilogue ----
    const float* dq2 = dq2_all ? dq2_all + n * BB : nullptr;
    const float* dk2 = dk2_all ? dk2_all + n * BB : nullptr;

    #pragma unroll
    for (int mi = 0; mi < 2; mi++) {
        const int m = row0 + wm * 32 + mi * 16 + lr;
        float b0 = 0.f, b1 = 0.f, dq0 = 0.f, dq1 = 0.f;
        if (MODE == 0) { b0 = bias[m]; b1 = bias[m + 8]; }
        if (MODE == 1) { dq0 = dq2[m]; dq1 = dq2[m + 8]; }

        #pragma unroll
        for (int ni = 0; ni < 8; ni++) {
            const int nn = col0 + wn * 64 + ni * 8 + 2 * lc;
            float v00 = acc[mi][ni][0], v01 = acc[mi][ni][1];
            float v10 = acc[mi][ni][2], v11 = acc[mi][ni][3];
            if (MODE == 0) {
                v00 += b0; v01 += b0; v10 += b1; v11 += b1;
            } else if (MODE == 1) {
                float dk0 = dk2[nn], dk1 = dk2[nn + 1];
                v00 *= rsqrtf(fmaxf(dq0 * dk0, EPS));
                v01 *= rsqrtf(fmaxf(dq0 * dk1, EPS));
                v10 *= rsqrtf(fmaxf(dq1 * dk0, EPS));
                v11 *= rsqrtf(fmaxf(dq1 * dk1, EPS));
            }
            *reinterpret_cast<float2*>(&Cn[(size_t)m * ldc + nn]) = make_float2(v00, v01);
            *reinterpret_cast<float2*>(&Cn[(size_t)(m + 8) * ldc + nn]) = make_float2(v10, v11);
        }
    }
}

// ---------------------------------------------------------------------------
// Stage 2: column squared norms of K and Q
// ---------------------------------------------------------------------------
__global__ __launch_bounds__(256)
void sq_kernel()
{
    int idx = blockIdx.x * 256 + threadIdx.x;
    int n = idx / BB;
    int b = idx % BB;
    const float* Kn = g_K + (size_t)n * CC * BB + b;
    const float* Qn = g_Q + (size_t)n * CC * BB + b;
    float sk = 0.f, sq = 0.f;
    #pragma unroll 4
    for (int c = 0; c < CC; c++) {
        float kv = Kn[(size_t)c * BB];
        float qv = Qn[(size_t)c * BB];
        sk = fmaf(kv, kv, sk);
        sq = fmaf(qv, qv, sq);
    }
    g_DK2[idx] = sk;
    g_DQ2[idx] = sq;
}

// ---------------------------------------------------------------------------
// Stage 4: softmax over b (axis=1) of Y[n,b,k], in place.
// ---------------------------------------------------------------------------
__global__ __launch_bounds__(256)
void softmax_kernel()
{
    const int n = blockIdx.y;
    const int k = blockIdx.x * 256 + threadIdx.x;
    float* Yn = g_Y + (size_t)n * BB * BB + k;

    float m = -INFINITY;
    #pragma unroll 4
    for (int b = 0; b < BB; b++)
        m = fmaxf(m, Yn[(size_t)b * BB]);

    float s = 0.f;
    #pragma unroll 4
    for (int b = 0; b < BB; b++) {
        float e = expf(Yn[(size_t)b * BB] - m);
        s += e;
        Yn[(size_t)b * BB] = e;
    }

    float inv = 1.f / s;
    #pragma unroll 4
    for (int b = 0; b < BB; b++)
        Yn[(size_t)b * BB] *= inv;
}

// ---------------------------------------------------------------------------
extern "C" void kernel_launch(void* const* d_in, const int* in_sizes, int n_in,
                              void* d_out, int out_size)
{
    const float* X    = (const float*)d_in[0];
    const float* Wk_w = (const float*)d_in[1];
    const float* Wk_b = (const float*)d_in[2];
    const float* Wq_w = (const float*)d_in[3];
    const float* Wq_b = (const float*)d_in[4];
    float* Z = (float*)d_out;

    float* Kd;  cudaGetSymbolAddress((void**)&Kd,  g_K);
    float* Qd;  cudaGetSymbolAddress((void**)&Qd,  g_Q);
    float* Yd;  cudaGetSymbolAddress((void**)&Yd,  g_Y);
    float* DK2; cudaGetSymbolAddress((void**)&DK2, g_DK2);
    float* DQ2; cudaGetSymbolAddress((void**)&DQ2, g_DQ2);

    const size_t sXn = (size_t)CC * BB;
    const size_t sYn = (size_t)BB * BB;

    // 1) projections: K = Wk@X + bk,  Q = Wq@X + bq   (MODE 0, A row-major)
    gemm_tf32<0, CC, false><<<dim3(BB / BN, CC / BM, NN), 256>>>(
        Wk_w, CC, 0, X, BB, sXn, Kd, BB, sXn, Wk_b, nullptr, nullptr);
    gemm_tf32<0, CC, false><<<dim3(BB / BN, CC / BM, NN), 256>>>(
        Wq_w, CC, 0, X, BB, sXn, Qd, BB, sXn, Wq_b, nullptr, nullptr);

    // 2) squared norms
    sq_kernel<<<(NN * BB) / 256, 256>>>();

    // 3) normalized scores: Y = Q^T @ K / sqrt(DQ2⊗DK2)  (MODE 1, A k-major)
    gemm_tf32<1, CC, true><<<dim3(BB / BN, BB / BM, NN), 256>>>(
        Qd, BB, sXn, Kd, BB, sXn, Yd, BB, sYn, nullptr, DQ2, DK2);

    // 4) softmax over query axis (in place)
    softmax_kernel<<<dim3(BB / 256, NN), 256>>>();

    // 5) output mix: Z = X @ SM   (MODE 2, A row-major)
    gemm_tf32<2, BB, false><<<dim3(BB / BN, CC / BM, NN), 256>>>(
        X, BB, sXn, Yd, BB, sYn, Z, BB, sXn, nullptr, nullptr, nullptr);
}